// round 10
// baseline (speedup 1.0000x reference)
#include <cuda_runtime.h>
#include <math.h>
#include <stdint.h>

#define NB    8
#define SEQL  1024
#define EMB   1024
#define NH    16
#define DH    64

// g_q: [(bh), seq, 64] tf32(q * log2e/32), paired-column layout
// g_k: [(bh), seq, 64] tf32, paired-column layout
// g_v: [(bh), 64, seq] tf32, transposed, seq-paired
// g_att: [n*seq, EMB] tf32, paired-column; g_wo: [EMB,EMB] tf32, paired-column
__device__ float g_q[NB*NH*SEQL*DH];
__device__ float g_k[NB*NH*SEQL*DH];
__device__ float g_v[NB*NH*SEQL*DH];
__device__ float g_att[NB*SEQL*EMB];
__device__ float g_wo[EMB*EMB];
__device__ unsigned g_mbits[NB*SEQL*32];     // bit-packed mask

#define QSCALE 0.04508422f        // log2(e) / 32

// ---------------------------------------------------------------------------
__device__ __forceinline__ float to_tf32(float x) {
    uint32_t u;
    asm("cvt.rna.tf32.f32 %0, %1;" : "=r"(u) : "f"(x));
    return __uint_as_float(u);
}
__device__ __forceinline__ float ex2f(float x) {
    float r;
    asm("ex2.approx.f32 %0, %1;" : "=f"(r) : "f"(x));
    return r;
}

__device__ __forceinline__ void mma8(float* c, const float* a, const float* b) {
    asm volatile(
        "mma.sync.aligned.m16n8k8.row.col.f32.tf32.tf32.f32 "
        "{%0,%1,%2,%3}, {%4,%5,%6,%7}, {%8,%9}, {%0,%1,%2,%3};"
        : "+f"(c[0]), "+f"(c[1]), "+f"(c[2]), "+f"(c[3])
        : "f"(a[0]), "f"(a[1]), "f"(a[2]), "f"(a[3]), "f"(b[0]), "f"(b[1]));
}

// ---------------------------------------------------------------------------
__global__ __launch_bounds__(256)
void mask_pack(const int* __restrict__ mask) {
    int w    = blockIdx.x * 8 + (threadIdx.x >> 5);
    int lane = threadIdx.x & 31;
    unsigned bit = mask[(size_t)w*32 + lane] != 0;
    unsigned word = __ballot_sync(0xffffffffu, bit);
    if (lane == 0) g_mbits[w] = word;
}

__global__ __launch_bounds__(256)
void wo_pack(const float* __restrict__ Wo) {
    int idx = blockIdx.x * 256 + threadIdx.x;
    int row = idx >> 8, ds = (idx & 255) * 4;
    float4 w = *(const float4*)(Wo + (size_t)row*EMB + ds);
    int pb = (ds & ~7) | ((ds >> 2) & 1);
    float* p = g_wo + (size_t)row*EMB + pb;
    p[0] = to_tf32(w.x); p[2] = to_tf32(w.y);
    p[4] = to_tf32(w.z); p[6] = to_tf32(w.w);
}

// ---------------------------------------------------------------------------
// Fused Q/K/V projection via 3xTF32 compensated mma (fp32-accurate).
// Epilogues: Q tf32(x*QSCALE) paired; K tf32 paired; V tf32 transposed seq-paired.
// ---------------------------------------------------------------------------
__global__ void __launch_bounds__(256, 2)
proj_mma(const float* __restrict__ xq, const float* __restrict__ xk,
         const float* __restrict__ xv,
         const float* __restrict__ Wq, const float* __restrict__ Wk,
         const float* __restrict__ Wv) {
    extern __shared__ float smp[];
    float* Xs  = smp;               // [128][72]
    float* Whi = smp + 128*72;      // [64][72]
    float* Wlo = Whi + 64*72;       // [64][72]

    int sel = blockIdx.z;
    const float* x = (sel == 0) ? xq : (sel == 1) ? xk : xv;
    const float* W = (sel == 0) ? Wq : (sel == 1) ? Wk : Wv;
    float*     out = (sel == 0) ? g_q : (sel == 1) ? g_k : g_v;

    int tid  = threadIdx.x;
    int lane = tid & 31, warp = tid >> 5;
    int g4 = lane >> 2, l4 = lane & 3;
    int wr = warp * 16;
    int rb = blockIdx.x, h = blockIdx.y;

    for (int g = tid; g < 1024; g += 256) {
        int e = g >> 4, ds = (g & 15) * 4;
        int pb = (ds & ~7) | ((ds >> 2) & 1);
        float4 w = *(const float4*)(W + e*64 + ds);
        float hx = to_tf32(w.x), hy = to_tf32(w.y), hz = to_tf32(w.z), hw = to_tf32(w.w);
        float* ph = &Whi[e*72 + pb];
        ph[0] = hx; ph[2] = hy; ph[4] = hz; ph[6] = hw;
        float* pl = &Wlo[e*72 + pb];
        pl[0] = to_tf32(w.x - hx); pl[2] = to_tf32(w.y - hy);
        pl[4] = to_tf32(w.z - hz); pl[6] = to_tf32(w.w - hw);
    }
    for (int g = tid; g < 2048; g += 256) {
        int row = g >> 4, ds = (g & 15) * 4;
        float4 v = *(const float4*)(x + (size_t)(rb*128 + row)*EMB + h*64 + ds);
        float* p = &Xs[row*72 + ((ds & ~7) | ((ds >> 2) & 1))];
        p[0] = v.x; p[2] = v.y; p[4] = v.z; p[6] = v.w;
    }
    __syncthreads();

    float ahi[8][4], alo[8][4];
    #pragma unroll
    for (int ks = 0; ks < 8; ks++) {
        float2 t0 = *(float2*)&Xs[(wr + g4    )*72 + ks*8 + l4*2];
        float2 t1 = *(float2*)&Xs[(wr + g4 + 8)*72 + ks*8 + l4*2];
        ahi[ks][0] = to_tf32(t0.x); alo[ks][0] = to_tf32(t0.x - ahi[ks][0]);
        ahi[ks][2] = to_tf32(t0.y); alo[ks][2] = to_tf32(t0.y - ahi[ks][2]);
        ahi[ks][1] = to_tf32(t1.x); alo[ks][1] = to_tf32(t1.x - ahi[ks][1]);
        ahi[ks][3] = to_tf32(t1.y); alo[ks][3] = to_tf32(t1.y - ahi[ks][3]);
    }

    float oacc[8][4];
    #pragma unroll
    for (int i = 0; i < 8; i++)
        #pragma unroll
        for (int j = 0; j < 4; j++) oacc[i][j] = 0.f;

    #pragma unroll
    for (int ks = 0; ks < 8; ks++) {
        #pragma unroll
        for (int nt = 0; nt < 8; nt++) {
            int bn = nt*8 + g4;
            float2 bh = *(float2*)&Whi[bn*72 + ks*8 + l4*2];
            float2 bl = *(float2*)&Wlo[bn*72 + ks*8 + l4*2];
            float vbh[2] = {bh.x, bh.y};
            float vbl[2] = {bl.x, bl.y};
            mma8(oacc[nt], ahi[ks], vbh);
            mma8(oacc[nt], alo[ks], vbh);
            mma8(oacc[nt], ahi[ks], vbl);
        }
    }

    int r0 = rb*128 + wr + g4;
    int r1 = r0 + 8;
    int n  = r0 >> 10;
    size_t base = ((size_t)(n*NH + h))*SEQL*DH;
    int l0 = r0 & 1023, l1 = r1 & 1023;

    if (sel < 2) {
        float scale = (sel == 0) ? QSCALE : 1.0f;
        float* o0 = out + base + (size_t)l0*DH;
        float* o1 = out + base + (size_t)l1*DH;
        int pc0 = 4*(l4 & 1) + (l4 >> 1);
        #pragma unroll
        for (int nt = 0; nt < 8; nt++) {
            int pc = nt*8 + pc0;
            o0[pc]   = to_tf32(oacc[nt][0] * scale);
            o0[pc+2] = to_tf32(oacc[nt][1] * scale);
            o1[pc]   = to_tf32(oacc[nt][2] * scale);
            o1[pc+2] = to_tf32(oacc[nt][3] * scale);
        }
    } else {
        // V: tf32, transposed [64][seq], seq-paired
        int sp0 = (l0 & ~7) + ((l0 & 3) << 1) + ((l0 >> 2) & 1);
        int sp1 = (l1 & ~7) + ((l1 & 3) << 1) + ((l1 >> 2) & 1);
        #pragma unroll
        for (int nt = 0; nt < 8; nt++) {
            int e = nt*8 + l4*2;
            out[base + (size_t)(e  )*SEQL + sp0] = to_tf32(oacc[nt][0]);
            out[base + (size_t)(e+1)*SEQL + sp0] = to_tf32(oacc[nt][1]);
            out[base + (size_t)(e  )*SEQL + sp1] = to_tf32(oacc[nt][2]);
            out[base + (size_t)(e+1)*SEQL + sp1] = to_tf32(oacc[nt][3]);
        }
    }
}

// ---------------------------------------------------------------------------
// Flash attention: pure-copy staging, ex2-only softmax, LDS.64 V fragments.
// ---------------------------------------------------------------------------
__global__ void __launch_bounds__(256, 2)
attn_mma_kernel() {
    extern __shared__ float sm[];
    float* Ks = sm;                     // [128][72] K (tf32 paired)
    float* Vt = sm + 128*72;            // [64][136] V^T (tf32 seq-paired)

    int tid  = threadIdx.x;
    int lane = tid & 31, warp = tid >> 5;
    int g4 = lane >> 2, l4 = lane & 3;
    int wr = warp * 16;
    int bh = blockIdx.y, n = bh >> 4, h = bh & 15, qb = blockIdx.x;

    const float* Qg = g_q + (size_t)bh*SEQL*DH + (size_t)qb*128*DH;
    const float* Kg = g_k + (size_t)bh*SEQL*DH;
    const float* Vg = g_v + (size_t)bh*SEQL*DH;   // [64][1024] seq-paired

    float qa[8][4];
    #pragma unroll
    for (int ks = 0; ks < 8; ks++) {
        float2 t0 = *(const float2*)(Qg + (wr + g4    )*DH + ks*8 + l4*2);
        float2 t1 = *(const float2*)(Qg + (wr + g4 + 8)*DH + ks*8 + l4*2);
        qa[ks][0] = t0.x; qa[ks][2] = t0.y;
        qa[ks][1] = t1.x; qa[ks][3] = t1.y;
    }

    float oacc[8][4];
    #pragma unroll
    for (int i = 0; i < 8; i++)
        #pragma unroll
        for (int j = 0; j < 4; j++) oacc[i][j] = 0.f;
    float rs0 = 0.f, rs1 = 0.f;

    int r0 = wr + g4, r1 = r0 + 8;
    const unsigned* mb0 = g_mbits + ((size_t)n*SEQL + qb*128 + r0)*32;
    const unsigned* mb1 = g_mbits + ((size_t)n*SEQL + qb*128 + r1)*32;

    int s0lane = g4*4 + (l4 >> 1);
    int s1lane = s0lane + 2;
    bool odd   = (l4 & 1);

    for (int jt = 0; jt < 8; jt++) {
        __syncthreads();
        const float4* Kt4 = (const float4*)(Kg + (size_t)jt*128*DH);
        #pragma unroll
        for (int it = 0; it < 8; it++) {
            int g = tid + 256*it;
            int row = g >> 4, ds = (g & 15) * 4;
            *(float4*)&Ks[row*72 + ds] = Kt4[g];
        }
        #pragma unroll
        for (int it = 0; it < 8; it++) {
            int g = tid + 256*it;
            int d = g >> 5, k4 = (g & 31) * 4;
            *(float4*)&Vt[d*136 + k4] = *(const float4*)(Vg + (size_t)d*SEQL + jt*128 + k4);
        }
        uint4 w0 = *(const uint4*)(mb0 + jt*4);
        uint4 w1 = *(const uint4*)(mb1 + jt*4);
        __syncthreads();

        #pragma unroll
        for (int half = 0; half < 2; half++) {
            float sc[8][4];
            #pragma unroll
            for (int nt = 0; nt < 8; nt++)
                sc[nt][0] = sc[nt][1] = sc[nt][2] = sc[nt][3] = 0.f;
            #pragma unroll
            for (int ks = 0; ks < 8; ks++) {
                #pragma unroll
                for (int nt = 0; nt < 8; nt++) {
                    int bn = (half*8 + nt)*8 + g4;
                    float2 tb = *(float2*)&Ks[bn*72 + ks*8 + l4*2];
                    float b[2] = {tb.x, tb.y};
                    mma8(sc[nt], qa[ks], b);
                }
            }

            // softmax: p = bit ? 2^s : 0   (log2e/32 pre-folded into Q)
            #pragma unroll
            for (int nt = 0; nt < 8; nt++) {
                int c = half*8 + nt;
                unsigned wd0 = (&w0.x)[c >> 2];
                unsigned wd1 = (&w1.x)[c >> 2];
                int bit = (c & 3)*8 + l4*2;
                sc[nt][0] = ((wd0 >> bit)     & 1) ? ex2f(sc[nt][0]) : 0.f;
                sc[nt][1] = ((wd0 >> (bit+1)) & 1) ? ex2f(sc[nt][1]) : 0.f;
                sc[nt][2] = ((wd1 >> bit)     & 1) ? ex2f(sc[nt][2]) : 0.f;
                sc[nt][3] = ((wd1 >> (bit+1)) & 1) ? ex2f(sc[nt][3]) : 0.f;
                rs0 += sc[nt][0] + sc[nt][1];
                rs1 += sc[nt][2] + sc[nt][3];
            }

            #pragma unroll
            for (int j = 0; j < 8; j++) {
                float q00 = __shfl_sync(0xffffffffu, sc[j][0], s0lane);
                float q01 = __shfl_sync(0xffffffffu, sc[j][1], s0lane);
                float q02 = __shfl_sync(0xffffffffu, sc[j][0], s1lane);
                float q03 = __shfl_sync(0xffffffffu, sc[j][1], s1lane);
                float q10 = __shfl_sync(0xffffffffu, sc[j][2], s0lane);
                float q11 = __shfl_sync(0xffffffffu, sc[j][3], s0lane);
                float q12 = __shfl_sync(0xffffffffu, sc[j][2], s1lane);
                float q13 = __shfl_sync(0xffffffffu, sc[j][3], s1lane);
                float pa[4];
                pa[0] = to_tf32(odd ? q01 : q00);
                pa[2] = to_tf32(odd ? q03 : q02);
                pa[1] = to_tf32(odd ? q11 : q10);
                pa[3] = to_tf32(odd ? q13 : q12);
                int kb = (half*8 + j)*8 + 2*l4;     // paired (kk, kk+4)
                #pragma unroll
                for (int nt8 = 0; nt8 < 8; nt8++) {
                    float2 tb = *(float2*)&Vt[(nt8*8 + g4)*136 + kb];
                    float b[2] = {tb.x, tb.y};
                    mma8(oacc[nt8], pa, b);
                }
            }
        }
    }

    rs0 += __shfl_xor_sync(0xffffffffu, rs0, 1);
    rs0 += __shfl_xor_sync(0xffffffffu, rs0, 2);
    rs1 += __shfl_xor_sync(0xffffffffu, rs1, 1);
    rs1 += __shfl_xor_sync(0xffffffffu, rs1, 2);
    float inv0 = 1.f / rs0, inv1 = 1.f / rs1;

    float* ob0 = g_att + ((size_t)(n*SEQL + qb*128 + r0))*EMB + h*DH;
    float* ob1 = g_att + ((size_t)(n*SEQL + qb*128 + r1))*EMB + h*DH;
    int pc0 = 4*(l4 & 1) + (l4 >> 1);
    #pragma unroll
    for (int nt = 0; nt < 8; nt++) {
        int pc = nt*8 + pc0;
        ob0[pc]   = to_tf32(oacc[nt][0]*inv0);
        ob0[pc+2] = to_tf32(oacc[nt][1]*inv0);
        ob1[pc]   = to_tf32(oacc[nt][2]*inv1);
        ob1[pc+2] = to_tf32(oacc[nt][3]*inv1);
    }
}

// ---------------------------------------------------------------------------
// Output projection: pure-copy staging (operands pre-converted/permuted).
// ---------------------------------------------------------------------------
__global__ __launch_bounds__(256, 2)
void outproj_mma(const float* __restrict__ bo, float* __restrict__ out) {
    extern __shared__ float smo[];
    float* As = smo;             // [128][72]
    float* Bs = smo + 128*72;    // [128][72]
    int tid  = threadIdx.x;
    int lane = tid & 31, warp = tid >> 5;
    int g4 = lane >> 2, l4 = lane & 3;
    int wr = (warp >> 1) * 32, wc = (warp & 1) * 64;
    int rb = blockIdx.y, cb = blockIdx.x;

    const float* A = g_att + (size_t)rb*128*EMB;
    const float* B = g_wo  + (size_t)cb*128*EMB;

    float acc[2][8][4];
    #pragma unroll
    for (int m = 0; m < 2; m++)
        #pragma unroll
        for (int i = 0; i < 8; i++)
            #pragma unroll
            for (int j = 0; j < 4; j++) acc[m][i][j] = 0.f;

    for (int kt = 0; kt < 16; kt++) {
        __syncthreads();
        #pragma unroll
        for (int it = 0; it < 8; it++) {
            int g = tid + 256*it;
            int row = g >> 4, ds = (g & 15) * 4;
            *(float4*)&As[row*72 + ds] = *(const float4*)(A + (size_t)row*EMB + kt*64 + ds);
            *(float4*)&Bs[row*72 + ds] = *(const float4*)(B + (size_t)row*EMB + kt*64 + ds);
        }
        __syncthreads();

        #pragma unroll
        for (int ks = 0; ks < 8; ks++) {
            int ko = ks*8 + l4*2;
            float a0[4], a1[4];
            float2 t;
            t = *(float2*)&As[(wr + g4     )*72 + ko]; a0[0] = t.x; a0[2] = t.y;
            t = *(float2*)&As[(wr + g4 + 8 )*72 + ko]; a0[1] = t.x; a0[3] = t.y;
            t = *(float2*)&As[(wr + g4 + 16)*72 + ko]; a1[0] = t.x; a1[2] = t.y;
            t = *(float2*)&As[(wr + g4 + 24)*72 + ko]; a1[1] = t.x; a1[3] = t.y;
            #pragma unroll
            for (int nt = 0; nt < 8; nt++) {
                float2 tb = *(float2*)&Bs[(wc + nt*8 + g4)*72 + ko];
                float b[2] = {tb.x, tb.y};
                mma8(acc[0][nt], a0, b);
                mma8(acc[1][nt], a1, b);
            }
        }
    }

    #pragma unroll
    for (int mt = 0; mt < 2; mt++) {
        #pragma unroll
        for (int nt = 0; nt < 8; nt++) {
            int c = cb*128 + wc + nt*8 + l4*2;
            float b0 = bo[c], b1 = bo[c+1];
            int r = rb*128 + wr + mt*16 + g4;
            *(float2*)&out[(size_t)r*EMB + c] =
                make_float2(acc[mt][nt][0] + b0, acc[mt][nt][1] + b1);
            *(float2*)&out[(size_t)(r+8)*EMB + c] =
                make_float2(acc[mt][nt][2] + b0, acc[mt][nt][3] + b1);
        }
    }
}

// ---------------------------------------------------------------------------
extern "C" void kernel_launch(void* const* d_in, const int* in_sizes, int n_in,
                              void* d_out, int out_size) {
    const float* values = (const float*)d_in[0];
    const float* keys   = (const float*)d_in[1];
    const float* query  = (const float*)d_in[2];
    const int*   mask   = (const int*)  d_in[3];
    const float* Wv     = (const float*)d_in[4];
    const float* Wk     = (const float*)d_in[5];
    const float* Wq     = (const float*)d_in[6];
    const float* Wo     = (const float*)d_in[7];
    const float* bo     = (const float*)d_in[8];
    float* out = (float*)d_out;

    mask_pack<<<NB*SEQL*32/8, 256>>>(mask);
    wo_pack<<<EMB*EMB/1024, 256>>>(Wo);

    int smem_p = (128*72 + 2*64*72) * (int)sizeof(float);   // 73728 B
    cudaFuncSetAttribute(proj_mma, cudaFuncAttributeMaxDynamicSharedMemorySize, smem_p);
    proj_mma<<<dim3(64, NH, 3), 256, smem_p>>>(query, keys, values, Wq, Wk, Wv);

    int smem = (128*72 + 64*136) * (int)sizeof(float);  // 71680 B
    cudaFuncSetAttribute(attn_mma_kernel, cudaFuncAttributeMaxDynamicSharedMemorySize, smem);
    attn_mma_kernel<<<dim3(SEQL/128, NB*NH), 256, smem>>>();

    int smem_o = 2 * 128*72 * (int)sizeof(float);       // 73728 B
    cudaFuncSetAttribute(outproj_mma, cudaFuncAttributeMaxDynamicSharedMemorySize, smem_o);
    outproj_mma<<<dim3(EMB/128, NB*SEQL/128), 256, smem_o>>>(bo, out);
}

// round 11
// speedup vs baseline: 1.0769x; 1.0769x over previous
#include <cuda_runtime.h>
#include <math.h>
#include <stdint.h>

#define NB    8
#define SEQL  1024
#define EMB   1024
#define NH    16
#define DH    64

// g_q: [(bh), seq, 64] tf32(q * log2e/32), paired-column layout
// g_k: [(bh), seq, 64] tf32, paired-column layout
// g_v: [(bh), 64, seq] tf32, transposed (plain seq order)
// g_att: [n*seq, EMB] tf32, paired-column; g_wo: [EMB,EMB] tf32, paired-column
__device__ float g_q[NB*NH*SEQL*DH];
__device__ float g_k[NB*NH*SEQL*DH];
__device__ float g_v[NB*NH*SEQL*DH];
__device__ float g_att[NB*SEQL*EMB];
__device__ float g_wo[EMB*EMB];
__device__ unsigned g_mbits[NB*SEQL*32];     // bit-packed mask

#define QSCALE 0.04508422f        // log2(e) / 32

// ---------------------------------------------------------------------------
__device__ __forceinline__ float to_tf32(float x) {
    uint32_t u;
    asm("cvt.rna.tf32.f32 %0, %1;" : "=r"(u) : "f"(x));
    return __uint_as_float(u);
}
__device__ __forceinline__ float ex2f(float x) {
    float r;
    asm("ex2.approx.f32 %0, %1;" : "=f"(r) : "f"(x));
    return r;
}

__device__ __forceinline__ void mma8(float* c, const float* a, const float* b) {
    asm volatile(
        "mma.sync.aligned.m16n8k8.row.col.f32.tf32.tf32.f32 "
        "{%0,%1,%2,%3}, {%4,%5,%6,%7}, {%8,%9}, {%0,%1,%2,%3};"
        : "+f"(c[0]), "+f"(c[1]), "+f"(c[2]), "+f"(c[3])
        : "f"(a[0]), "f"(a[1]), "f"(a[2]), "f"(a[3]), "f"(b[0]), "f"(b[1]));
}

// ---------------------------------------------------------------------------
__global__ __launch_bounds__(256)
void mask_pack(const int* __restrict__ mask) {
    int w    = blockIdx.x * 8 + (threadIdx.x >> 5);
    int lane = threadIdx.x & 31;
    unsigned bit = mask[(size_t)w*32 + lane] != 0;
    unsigned word = __ballot_sync(0xffffffffu, bit);
    if (lane == 0) g_mbits[w] = word;
}

__global__ __launch_bounds__(256)
void wo_pack(const float* __restrict__ Wo) {
    int idx = blockIdx.x * 256 + threadIdx.x;
    int row = idx >> 8, ds = (idx & 255) * 4;
    float4 w = *(const float4*)(Wo + (size_t)row*EMB + ds);
    int pb = (ds & ~7) | ((ds >> 2) & 1);
    float* p = g_wo + (size_t)row*EMB + pb;
    p[0] = to_tf32(w.x); p[2] = to_tf32(w.y);
    p[4] = to_tf32(w.z); p[6] = to_tf32(w.w);
}

// ---------------------------------------------------------------------------
// Fused Q/K/V projection via 3xTF32 compensated mma (fp32-accurate).
// Epilogues: Q tf32(x*QSCALE) paired; K tf32 paired; V tf32 transposed (plain).
// ---------------------------------------------------------------------------
__global__ void __launch_bounds__(256, 2)
proj_mma(const float* __restrict__ xq, const float* __restrict__ xk,
         const float* __restrict__ xv,
         const float* __restrict__ Wq, const float* __restrict__ Wk,
         const float* __restrict__ Wv) {
    extern __shared__ float smp[];
    float* Xs  = smp;               // [128][72]
    float* Whi = smp + 128*72;      // [64][72]
    float* Wlo = Whi + 64*72;       // [64][72]

    int sel = blockIdx.z;
    const float* x = (sel == 0) ? xq : (sel == 1) ? xk : xv;
    const float* W = (sel == 0) ? Wq : (sel == 1) ? Wk : Wv;
    float*     out = (sel == 0) ? g_q : (sel == 1) ? g_k : g_v;

    int tid  = threadIdx.x;
    int lane = tid & 31, warp = tid >> 5;
    int g4 = lane >> 2, l4 = lane & 3;
    int wr = warp * 16;
    int rb = blockIdx.x, h = blockIdx.y;

    for (int g = tid; g < 1024; g += 256) {
        int e = g >> 4, ds = (g & 15) * 4;
        int pb = (ds & ~7) | ((ds >> 2) & 1);
        float4 w = *(const float4*)(W + e*64 + ds);
        float hx = to_tf32(w.x), hy = to_tf32(w.y), hz = to_tf32(w.z), hw = to_tf32(w.w);
        float* ph = &Whi[e*72 + pb];
        ph[0] = hx; ph[2] = hy; ph[4] = hz; ph[6] = hw;
        float* pl = &Wlo[e*72 + pb];
        pl[0] = to_tf32(w.x - hx); pl[2] = to_tf32(w.y - hy);
        pl[4] = to_tf32(w.z - hz); pl[6] = to_tf32(w.w - hw);
    }
    for (int g = tid; g < 2048; g += 256) {
        int row = g >> 4, ds = (g & 15) * 4;
        float4 v = *(const float4*)(x + (size_t)(rb*128 + row)*EMB + h*64 + ds);
        float* p = &Xs[row*72 + ((ds & ~7) | ((ds >> 2) & 1))];
        p[0] = v.x; p[2] = v.y; p[4] = v.z; p[6] = v.w;
    }
    __syncthreads();

    float ahi[8][4], alo[8][4];
    #pragma unroll
    for (int ks = 0; ks < 8; ks++) {
        float2 t0 = *(float2*)&Xs[(wr + g4    )*72 + ks*8 + l4*2];
        float2 t1 = *(float2*)&Xs[(wr + g4 + 8)*72 + ks*8 + l4*2];
        ahi[ks][0] = to_tf32(t0.x); alo[ks][0] = to_tf32(t0.x - ahi[ks][0]);
        ahi[ks][2] = to_tf32(t0.y); alo[ks][2] = to_tf32(t0.y - ahi[ks][2]);
        ahi[ks][1] = to_tf32(t1.x); alo[ks][1] = to_tf32(t1.x - ahi[ks][1]);
        ahi[ks][3] = to_tf32(t1.y); alo[ks][3] = to_tf32(t1.y - ahi[ks][3]);
    }

    float oacc[8][4];
    #pragma unroll
    for (int i = 0; i < 8; i++)
        #pragma unroll
        for (int j = 0; j < 4; j++) oacc[i][j] = 0.f;

    #pragma unroll
    for (int ks = 0; ks < 8; ks++) {
        #pragma unroll
        for (int nt = 0; nt < 8; nt++) {
            int bn = nt*8 + g4;
            float2 bh = *(float2*)&Whi[bn*72 + ks*8 + l4*2];
            float2 bl = *(float2*)&Wlo[bn*72 + ks*8 + l4*2];
            float vbh[2] = {bh.x, bh.y};
            float vbl[2] = {bl.x, bl.y};
            mma8(oacc[nt], ahi[ks], vbh);
            mma8(oacc[nt], alo[ks], vbh);
            mma8(oacc[nt], ahi[ks], vbl);
        }
    }

    int r0 = rb*128 + wr + g4;
    int r1 = r0 + 8;
    int n  = r0 >> 10;
    size_t base = ((size_t)(n*NH + h))*SEQL*DH;
    int l0 = r0 & 1023, l1 = r1 & 1023;

    if (sel < 2) {
        float scale = (sel == 0) ? QSCALE : 1.0f;
        float* o0 = out + base + (size_t)l0*DH;
        float* o1 = out + base + (size_t)l1*DH;
        int pc0 = 4*(l4 & 1) + (l4 >> 1);
        #pragma unroll
        for (int nt = 0; nt < 8; nt++) {
            int pc = nt*8 + pc0;
            o0[pc]   = to_tf32(oacc[nt][0] * scale);
            o0[pc+2] = to_tf32(oacc[nt][1] * scale);
            o1[pc]   = to_tf32(oacc[nt][2] * scale);
            o1[pc+2] = to_tf32(oacc[nt][3] * scale);
        }
    } else {
        // V: tf32, transposed [64][seq], plain seq order
        #pragma unroll
        for (int nt = 0; nt < 8; nt++) {
            int e = nt*8 + l4*2;
            out[base + (size_t)(e  )*SEQL + l0] = to_tf32(oacc[nt][0]);
            out[base + (size_t)(e+1)*SEQL + l0] = to_tf32(oacc[nt][1]);
            out[base + (size_t)(e  )*SEQL + l1] = to_tf32(oacc[nt][2]);
            out[base + (size_t)(e+1)*SEQL + l1] = to_tf32(oacc[nt][3]);
        }
    }
}

// ---------------------------------------------------------------------------
// Flash attention: shuffle-free P->A via contraction-index permutation
// (A slot l4 <-> P col 2*l4; B slot l4 <-> V seq 2*l4 — adjacent, LDS.64).
// ---------------------------------------------------------------------------
__global__ void __launch_bounds__(256, 2)
attn_mma_kernel() {
    extern __shared__ float sm[];
    float* Ks = sm;                     // [128][72] K (tf32 paired)
    float* Vt = sm + 128*72;            // [64][136] V^T (tf32 plain)

    int tid  = threadIdx.x;
    int lane = tid & 31, warp = tid >> 5;
    int g4 = lane >> 2, l4 = lane & 3;
    int wr = warp * 16;
    int bh = blockIdx.y, n = bh >> 4, h = bh & 15, qb = blockIdx.x;

    const float* Qg = g_q + (size_t)bh*SEQL*DH + (size_t)qb*128*DH;
    const float* Kg = g_k + (size_t)bh*SEQL*DH;
    const float* Vg = g_v + (size_t)bh*SEQL*DH;   // [64][1024]

    float qa[8][4];
    #pragma unroll
    for (int ks = 0; ks < 8; ks++) {
        float2 t0 = *(const float2*)(Qg + (wr + g4    )*DH + ks*8 + l4*2);
        float2 t1 = *(const float2*)(Qg + (wr + g4 + 8)*DH + ks*8 + l4*2);
        qa[ks][0] = t0.x; qa[ks][2] = t0.y;
        qa[ks][1] = t1.x; qa[ks][3] = t1.y;
    }

    float oacc[8][4];
    #pragma unroll
    for (int i = 0; i < 8; i++)
        #pragma unroll
        for (int j = 0; j < 4; j++) oacc[i][j] = 0.f;
    float rs0 = 0.f, rs1 = 0.f;

    int r0 = wr + g4, r1 = r0 + 8;
    const unsigned* mb0 = g_mbits + ((size_t)n*SEQL + qb*128 + r0)*32;
    const unsigned* mb1 = g_mbits + ((size_t)n*SEQL + qb*128 + r1)*32;

    for (int jt = 0; jt < 8; jt++) {
        __syncthreads();
        const float4* Kt4 = (const float4*)(Kg + (size_t)jt*128*DH);
        #pragma unroll
        for (int it = 0; it < 8; it++) {
            int g = tid + 256*it;
            int row = g >> 4, ds = (g & 15) * 4;
            *(float4*)&Ks[row*72 + ds] = Kt4[g];
        }
        #pragma unroll
        for (int it = 0; it < 8; it++) {
            int g = tid + 256*it;
            int d = g >> 5, k4 = (g & 31) * 4;
            *(float4*)&Vt[d*136 + k4] = *(const float4*)(Vg + (size_t)d*SEQL + jt*128 + k4);
        }
        uint4 w0 = *(const uint4*)(mb0 + jt*4);
        uint4 w1 = *(const uint4*)(mb1 + jt*4);
        __syncthreads();

        #pragma unroll
        for (int half = 0; half < 2; half++) {
            float sc[8][4];
            #pragma unroll
            for (int nt = 0; nt < 8; nt++)
                sc[nt][0] = sc[nt][1] = sc[nt][2] = sc[nt][3] = 0.f;
            #pragma unroll
            for (int ks = 0; ks < 8; ks++) {
                #pragma unroll
                for (int nt = 0; nt < 8; nt++) {
                    int bn = (half*8 + nt)*8 + g4;
                    float2 tb = *(float2*)&Ks[bn*72 + ks*8 + l4*2];
                    float b[2] = {tb.x, tb.y};
                    mma8(sc[nt], qa[ks], b);
                }
            }

            // softmax: p = bit ? 2^s : 0   (log2e/32 pre-folded into Q)
            #pragma unroll
            for (int nt = 0; nt < 8; nt++) {
                int c = half*8 + nt;
                unsigned wd0 = (&w0.x)[c >> 2];
                unsigned wd1 = (&w1.x)[c >> 2];
                int bit = (c & 3)*8 + l4*2;
                sc[nt][0] = ((wd0 >> bit)     & 1) ? ex2f(sc[nt][0]) : 0.f;
                sc[nt][1] = ((wd0 >> (bit+1)) & 1) ? ex2f(sc[nt][1]) : 0.f;
                sc[nt][2] = ((wd1 >> bit)     & 1) ? ex2f(sc[nt][2]) : 0.f;
                sc[nt][3] = ((wd1 >> (bit+1)) & 1) ? ex2f(sc[nt][3]) : 0.f;
                rs0 += sc[nt][0] + sc[nt][1];
                rs1 += sc[nt][2] + sc[nt][3];
            }

            // PV: A = D-fragment register rename (no shuffles).
            // A slot k'=l4 holds P col 2l4; B slot k'=l4 holds V seq 2l4.
            #pragma unroll
            for (int j = 0; j < 8; j++) {
                float pa[4];
                pa[0] = to_tf32(sc[j][0]);     // A[g4   ][k' l4  ] = P[r0][2l4]
                pa[1] = to_tf32(sc[j][2]);     // A[g4+8 ][k' l4  ] = P[r1][2l4]
                pa[2] = to_tf32(sc[j][1]);     // A[g4   ][k' l4+4] = P[r0][2l4+1]
                pa[3] = to_tf32(sc[j][3]);     // A[g4+8 ][k' l4+4] = P[r1][2l4+1]
                int kb = (half*8 + j)*8 + 2*l4;
                #pragma unroll
                for (int nt8 = 0; nt8 < 8; nt8++) {
                    float2 tb = *(float2*)&Vt[(nt8*8 + g4)*136 + kb];
                    float b[2] = {tb.x, tb.y};
                    mma8(oacc[nt8], pa, b);
                }
            }
        }
    }

    rs0 += __shfl_xor_sync(0xffffffffu, rs0, 1);
    rs0 += __shfl_xor_sync(0xffffffffu, rs0, 2);
    rs1 += __shfl_xor_sync(0xffffffffu, rs1, 1);
    rs1 += __shfl_xor_sync(0xffffffffu, rs1, 2);
    float inv0 = 1.f / rs0, inv1 = 1.f / rs1;

    float* ob0 = g_att + ((size_t)(n*SEQL + qb*128 + r0))*EMB + h*DH;
    float* ob1 = g_att + ((size_t)(n*SEQL + qb*128 + r1))*EMB + h*DH;
    int pc0 = 4*(l4 & 1) + (l4 >> 1);
    #pragma unroll
    for (int nt = 0; nt < 8; nt++) {
        int pc = nt*8 + pc0;
        ob0[pc]   = to_tf32(oacc[nt][0]*inv0);
        ob0[pc+2] = to_tf32(oacc[nt][1]*inv0);
        ob1[pc]   = to_tf32(oacc[nt][2]*inv1);
        ob1[pc+2] = to_tf32(oacc[nt][3]*inv1);
    }
}

// ---------------------------------------------------------------------------
// Output projection: pure-copy staging (operands pre-converted/permuted).
// ---------------------------------------------------------------------------
__global__ __launch_bounds__(256, 2)
void outproj_mma(const float* __restrict__ bo, float* __restrict__ out) {
    extern __shared__ float smo[];
    float* As = smo;             // [128][72]
    float* Bs = smo + 128*72;    // [128][72]
    int tid  = threadIdx.x;
    int lane = tid & 31, warp = tid >> 5;
    int g4 = lane >> 2, l4 = lane & 3;
    int wr = (warp >> 1) * 32, wc = (warp & 1) * 64;
    int rb = blockIdx.y, cb = blockIdx.x;

    const float* A = g_att + (size_t)rb*128*EMB;
    const float* B = g_wo  + (size_t)cb*128*EMB;

    float acc[2][8][4];
    #pragma unroll
    for (int m = 0; m < 2; m++)
        #pragma unroll
        for (int i = 0; i < 8; i++)
            #pragma unroll
            for (int j = 0; j < 4; j++) acc[m][i][j] = 0.f;

    for (int kt = 0; kt < 16; kt++) {
        __syncthreads();
        #pragma unroll
        for (int it = 0; it < 8; it++) {
            int g = tid + 256*it;
            int row = g >> 4, ds = (g & 15) * 4;
            *(float4*)&As[row*72 + ds] = *(const float4*)(A + (size_t)row*EMB + kt*64 + ds);
            *(float4*)&Bs[row*72 + ds] = *(const float4*)(B + (size_t)row*EMB + kt*64 + ds);
        }
        __syncthreads();

        #pragma unroll
        for (int ks = 0; ks < 8; ks++) {
            int ko = ks*8 + l4*2;
            float a0[4], a1[4];
            float2 t;
            t = *(float2*)&As[(wr + g4     )*72 + ko]; a0[0] = t.x; a0[2] = t.y;
            t = *(float2*)&As[(wr + g4 + 8 )*72 + ko]; a0[1] = t.x; a0[3] = t.y;
            t = *(float2*)&As[(wr + g4 + 16)*72 + ko]; a1[0] = t.x; a1[2] = t.y;
            t = *(float2*)&As[(wr + g4 + 24)*72 + ko]; a1[1] = t.x; a1[3] = t.y;
            #pragma unroll
            for (int nt = 0; nt < 8; nt++) {
                float2 tb = *(float2*)&Bs[(wc + nt*8 + g4)*72 + ko];
                float b[2] = {tb.x, tb.y};
                mma8(acc[0][nt], a0, b);
                mma8(acc[1][nt], a1, b);
            }
        }
    }

    #pragma unroll
    for (int mt = 0; mt < 2; mt++) {
        #pragma unroll
        for (int nt = 0; nt < 8; nt++) {
            int c = cb*128 + wc + nt*8 + l4*2;
            float b0 = bo[c], b1 = bo[c+1];
            int r = rb*128 + wr + mt*16 + g4;
            *(float2*)&out[(size_t)r*EMB + c] =
                make_float2(acc[mt][nt][0] + b0, acc[mt][nt][1] + b1);
            *(float2*)&out[(size_t)(r+8)*EMB + c] =
                make_float2(acc[mt][nt][2] + b0, acc[mt][nt][3] + b1);
        }
    }
}

// ---------------------------------------------------------------------------
extern "C" void kernel_launch(void* const* d_in, const int* in_sizes, int n_in,
                              void* d_out, int out_size) {
    const float* values = (const float*)d_in[0];
    const float* keys   = (const float*)d_in[1];
    const float* query  = (const float*)d_in[2];
    const int*   mask   = (const int*)  d_in[3];
    const float* Wv     = (const float*)d_in[4];
    const float* Wk     = (const float*)d_in[5];
    const float* Wq     = (const float*)d_in[6];
    const float* Wo     = (const float*)d_in[7];
    const float* bo     = (const float*)d_in[8];
    float* out = (float*)d_out;

    mask_pack<<<NB*SEQL*32/8, 256>>>(mask);
    wo_pack<<<EMB*EMB/1024, 256>>>(Wo);

    int smem_p = (128*72 + 2*64*72) * (int)sizeof(float);   // 73728 B
    cudaFuncSetAttribute(proj_mma, cudaFuncAttributeMaxDynamicSharedMemorySize, smem_p);
    proj_mma<<<dim3(64, NH, 3), 256, smem_p>>>(query, keys, values, Wq, Wk, Wv);

    int smem = (128*72 + 64*136) * (int)sizeof(float);  // 71680 B
    cudaFuncSetAttribute(attn_mma_kernel, cudaFuncAttributeMaxDynamicSharedMemorySize, smem);
    attn_mma_kernel<<<dim3(SEQL/128, NB*NH), 256, smem>>>();

    int smem_o = 2 * 128*72 * (int)sizeof(float);       // 73728 B
    cudaFuncSetAttribute(outproj_mma, cudaFuncAttributeMaxDynamicSharedMemorySize, smem_o);
    outproj_mma<<<dim3(EMB/128, NB*SEQL/128), 256, smem_o>>>(bo, out);
}

// round 12
// speedup vs baseline: 1.1299x; 1.0492x over previous
#include <cuda_runtime.h>
#include <math.h>
#include <stdint.h>

#define NB    8
#define SEQL  1024
#define EMB   1024
#define NH    16
#define DH    64

// g_q: [(bh), seq, 64] tf32(q * log2e/32), paired-column layout
// g_k: [(bh), seq, 64] tf32, paired-column layout
// g_v: [(bh), 64, seq] tf32, transposed (plain seq order)
// g_att: [n*seq, EMB] tf32, paired-column; g_wo: [EMB,EMB] tf32, paired-column
__device__ float g_q[NB*NH*SEQL*DH];
__device__ float g_k[NB*NH*SEQL*DH];
__device__ float g_v[NB*NH*SEQL*DH];
__device__ float g_att[NB*SEQL*EMB];
__device__ float g_wo[EMB*EMB];
__device__ unsigned g_mbits[NB*SEQL*32];     // bit-packed mask

#define QSCALE 0.04508422f        // log2(e) / 32

// ---------------------------------------------------------------------------
__device__ __forceinline__ float to_tf32(float x) {
    uint32_t u;
    asm("cvt.rna.tf32.f32 %0, %1;" : "=r"(u) : "f"(x));
    return __uint_as_float(u);
}
__device__ __forceinline__ float ex2f(float x) {
    float r;
    asm("ex2.approx.f32 %0, %1;" : "=f"(r) : "f"(x));
    return r;
}
__device__ __forceinline__ uint32_t smem_u32(const void* p) {
    uint32_t a;
    asm("{ .reg .u64 t; cvta.to.shared.u64 t, %1; cvt.u32.u64 %0, t; }" : "=r"(a) : "l"(p));
    return a;
}
__device__ __forceinline__ void cpasync16(uint32_t saddr, const void* gptr) {
    asm volatile("cp.async.cg.shared.global [%0], [%1], 16;" :: "r"(saddr), "l"(gptr));
}
#define CP_COMMIT() asm volatile("cp.async.commit_group;" ::: "memory")
#define CP_WAIT(n)  asm volatile("cp.async.wait_group %0;" :: "n"(n) : "memory")

__device__ __forceinline__ void mma8(float* c, const float* a, const float* b) {
    asm volatile(
        "mma.sync.aligned.m16n8k8.row.col.f32.tf32.tf32.f32 "
        "{%0,%1,%2,%3}, {%4,%5,%6,%7}, {%8,%9}, {%0,%1,%2,%3};"
        : "+f"(c[0]), "+f"(c[1]), "+f"(c[2]), "+f"(c[3])
        : "f"(a[0]), "f"(a[1]), "f"(a[2]), "f"(a[3]), "f"(b[0]), "f"(b[1]));
}

// ---------------------------------------------------------------------------
__global__ __launch_bounds__(256)
void mask_pack(const int* __restrict__ mask) {
    int w    = blockIdx.x * 8 + (threadIdx.x >> 5);
    int lane = threadIdx.x & 31;
    unsigned bit = mask[(size_t)w*32 + lane] != 0;
    unsigned word = __ballot_sync(0xffffffffu, bit);
    if (lane == 0) g_mbits[w] = word;
}

__global__ __launch_bounds__(256)
void wo_pack(const float* __restrict__ Wo) {
    int idx = blockIdx.x * 256 + threadIdx.x;
    int row = idx >> 8, ds = (idx & 255) * 4;
    float4 w = *(const float4*)(Wo + (size_t)row*EMB + ds);
    int pb = (ds & ~7) | ((ds >> 2) & 1);
    float* p = g_wo + (size_t)row*EMB + pb;
    p[0] = to_tf32(w.x); p[2] = to_tf32(w.y);
    p[4] = to_tf32(w.z); p[6] = to_tf32(w.w);
}

// ---------------------------------------------------------------------------
// Fused Q/K/V projection via 3xTF32 compensated mma (fp32-accurate).
// Epilogues: Q tf32(x*QSCALE) paired; K tf32 paired; V tf32 transposed (plain).
// ---------------------------------------------------------------------------
__global__ void __launch_bounds__(256, 2)
proj_mma(const float* __restrict__ xq, const float* __restrict__ xk,
         const float* __restrict__ xv,
         const float* __restrict__ Wq, const float* __restrict__ Wk,
         const float* __restrict__ Wv) {
    extern __shared__ float smp[];
    float* Xs  = smp;               // [128][72]
    float* Whi = smp + 128*72;      // [64][72]
    float* Wlo = Whi + 64*72;       // [64][72]

    int sel = blockIdx.z;
    const float* x = (sel == 0) ? xq : (sel == 1) ? xk : xv;
    const float* W = (sel == 0) ? Wq : (sel == 1) ? Wk : Wv;
    float*     out = (sel == 0) ? g_q : (sel == 1) ? g_k : g_v;

    int tid  = threadIdx.x;
    int lane = tid & 31, warp = tid >> 5;
    int g4 = lane >> 2, l4 = lane & 3;
    int wr = warp * 16;
    int rb = blockIdx.x, h = blockIdx.y;

    for (int g = tid; g < 1024; g += 256) {
        int e = g >> 4, ds = (g & 15) * 4;
        int pb = (ds & ~7) | ((ds >> 2) & 1);
        float4 w = *(const float4*)(W + e*64 + ds);
        float hx = to_tf32(w.x), hy = to_tf32(w.y), hz = to_tf32(w.z), hw = to_tf32(w.w);
        float* ph = &Whi[e*72 + pb];
        ph[0] = hx; ph[2] = hy; ph[4] = hz; ph[6] = hw;
        float* pl = &Wlo[e*72 + pb];
        pl[0] = to_tf32(w.x - hx); pl[2] = to_tf32(w.y - hy);
        pl[4] = to_tf32(w.z - hz); pl[6] = to_tf32(w.w - hw);
    }
    for (int g = tid; g < 2048; g += 256) {
        int row = g >> 4, ds = (g & 15) * 4;
        float4 v = *(const float4*)(x + (size_t)(rb*128 + row)*EMB + h*64 + ds);
        float* p = &Xs[row*72 + ((ds & ~7) | ((ds >> 2) & 1))];
        p[0] = v.x; p[2] = v.y; p[4] = v.z; p[6] = v.w;
    }
    __syncthreads();

    float ahi[8][4], alo[8][4];
    #pragma unroll
    for (int ks = 0; ks < 8; ks++) {
        float2 t0 = *(float2*)&Xs[(wr + g4    )*72 + ks*8 + l4*2];
        float2 t1 = *(float2*)&Xs[(wr + g4 + 8)*72 + ks*8 + l4*2];
        ahi[ks][0] = to_tf32(t0.x); alo[ks][0] = to_tf32(t0.x - ahi[ks][0]);
        ahi[ks][2] = to_tf32(t0.y); alo[ks][2] = to_tf32(t0.y - ahi[ks][2]);
        ahi[ks][1] = to_tf32(t1.x); alo[ks][1] = to_tf32(t1.x - ahi[ks][1]);
        ahi[ks][3] = to_tf32(t1.y); alo[ks][3] = to_tf32(t1.y - ahi[ks][3]);
    }

    float oacc[8][4];
    #pragma unroll
    for (int i = 0; i < 8; i++)
        #pragma unroll
        for (int j = 0; j < 4; j++) oacc[i][j] = 0.f;

    #pragma unroll
    for (int ks = 0; ks < 8; ks++) {
        #pragma unroll
        for (int nt = 0; nt < 8; nt++) {
            int bn = nt*8 + g4;
            float2 bh = *(float2*)&Whi[bn*72 + ks*8 + l4*2];
            float2 bl = *(float2*)&Wlo[bn*72 + ks*8 + l4*2];
            float vbh[2] = {bh.x, bh.y};
            float vbl[2] = {bl.x, bl.y};
            mma8(oacc[nt], ahi[ks], vbh);
            mma8(oacc[nt], alo[ks], vbh);
            mma8(oacc[nt], ahi[ks], vbl);
        }
    }

    int r0 = rb*128 + wr + g4;
    int r1 = r0 + 8;
    int n  = r0 >> 10;
    size_t base = ((size_t)(n*NH + h))*SEQL*DH;
    int l0 = r0 & 1023, l1 = r1 & 1023;

    if (sel < 2) {
        float scale = (sel == 0) ? QSCALE : 1.0f;
        float* o0 = out + base + (size_t)l0*DH;
        float* o1 = out + base + (size_t)l1*DH;
        int pc0 = 4*(l4 & 1) + (l4 >> 1);
        #pragma unroll
        for (int nt = 0; nt < 8; nt++) {
            int pc = nt*8 + pc0;
            o0[pc]   = to_tf32(oacc[nt][0] * scale);
            o0[pc+2] = to_tf32(oacc[nt][1] * scale);
            o1[pc]   = to_tf32(oacc[nt][2] * scale);
            o1[pc+2] = to_tf32(oacc[nt][3] * scale);
        }
    } else {
        // V: tf32, transposed [64][seq], plain seq order
        #pragma unroll
        for (int nt = 0; nt < 8; nt++) {
            int e = nt*8 + l4*2;
            out[base + (size_t)(e  )*SEQL + l0] = to_tf32(oacc[nt][0]);
            out[base + (size_t)(e+1)*SEQL + l0] = to_tf32(oacc[nt][1]);
            out[base + (size_t)(e  )*SEQL + l1] = to_tf32(oacc[nt][2]);
            out[base + (size_t)(e+1)*SEQL + l1] = to_tf32(oacc[nt][3]);
        }
    }
}

// ---------------------------------------------------------------------------
// Flash attention: cp.async pipeline (double-buffered K, split-wait V),
// shuffle-free P->A contraction permutation.
//   SMEM: kbuf[2] 128x72 each, vbuf 64x136.
//   Groups per jt: [V(jt)] then [K(jt+1)]; wait 2 before S, wait 1 before PV.
// ---------------------------------------------------------------------------
#define KSLOT 9216        // floats per K slot (128*72)
#define VOFF  18432       // float offset of V buffer

__global__ void __launch_bounds__(256, 2)
attn_mma_kernel() {
    extern __shared__ float sm[];

    int tid  = threadIdx.x;
    int lane = tid & 31, warp = tid >> 5;
    int g4 = lane >> 2, l4 = lane & 3;
    int wr = warp * 16;
    int bh = blockIdx.y, n = bh >> 4, h = bh & 15, qb = blockIdx.x;

    const float* Qg = g_q + (size_t)bh*SEQL*DH + (size_t)qb*128*DH;
    const float* Kg = g_k + (size_t)bh*SEQL*DH;
    const float* Vg = g_v + (size_t)bh*SEQL*DH;   // [64][1024]

    uint32_t sbase = smem_u32(sm);
    // per-thread K staging offsets (8 float4 each)
    int krow[8], kds[8], vd[8], vk4[8];
    #pragma unroll
    for (int it = 0; it < 8; it++) {
        int g = tid + 256*it;
        krow[it] = g >> 4; kds[it] = (g & 15) * 4;
        vd[it]   = g >> 5; vk4[it] = (g & 31) * 4;
    }

    // Prologue: K(0) -> slot 0
    #pragma unroll
    for (int it = 0; it < 8; it++)
        cpasync16(sbase + (uint32_t)(krow[it]*72 + kds[it])*4,
                  Kg + (size_t)krow[it]*DH + kds[it]);
    CP_COMMIT();

    // Q fragments direct from global (paired layout)
    float qa[8][4];
    #pragma unroll
    for (int ks = 0; ks < 8; ks++) {
        float2 t0 = *(const float2*)(Qg + (wr + g4    )*DH + ks*8 + l4*2);
        float2 t1 = *(const float2*)(Qg + (wr + g4 + 8)*DH + ks*8 + l4*2);
        qa[ks][0] = t0.x; qa[ks][2] = t0.y;
        qa[ks][1] = t1.x; qa[ks][3] = t1.y;
    }

    float oacc[8][4];
    #pragma unroll
    for (int i = 0; i < 8; i++)
        #pragma unroll
        for (int j = 0; j < 4; j++) oacc[i][j] = 0.f;
    float rs0 = 0.f, rs1 = 0.f;

    int r0 = wr + g4, r1 = r0 + 8;
    const unsigned* mb0 = g_mbits + ((size_t)n*SEQL + qb*128 + r0)*32;
    const unsigned* mb1 = g_mbits + ((size_t)n*SEQL + qb*128 + r1)*32;

    float* Vt = sm + VOFF;

    for (int jt = 0; jt < 8; jt++) {
        __syncthreads();     // all warps done with vbuf + K slot (jt+1)&1

        // group A: V(jt)
        #pragma unroll
        for (int it = 0; it < 8; it++)
            cpasync16(sbase + (uint32_t)(VOFF + vd[it]*136 + vk4[it])*4,
                      Vg + (size_t)vd[it]*SEQL + jt*128 + vk4[it]);
        CP_COMMIT();
        // group B: K(jt+1)
        if (jt < 7) {
            uint32_t kb = (uint32_t)(((jt+1) & 1) * KSLOT);
            const float* Kn = Kg + (size_t)(jt+1)*128*DH;
            #pragma unroll
            for (int it = 0; it < 8; it++)
                cpasync16(sbase + (kb + (uint32_t)(krow[it]*72 + kds[it]))*4,
                          Kn + (size_t)krow[it]*DH + kds[it]);
        }
        CP_COMMIT();

        uint4 w0 = *(const uint4*)(mb0 + jt*4);
        uint4 w1 = *(const uint4*)(mb1 + jt*4);

        CP_WAIT(2);          // K(jt) complete
        __syncthreads();
        float* Ks = sm + (jt & 1) * KSLOT;

        #pragma unroll
        for (int half = 0; half < 2; half++) {
            float sc[8][4];
            #pragma unroll
            for (int nt = 0; nt < 8; nt++)
                sc[nt][0] = sc[nt][1] = sc[nt][2] = sc[nt][3] = 0.f;
            #pragma unroll
            for (int ks = 0; ks < 8; ks++) {
                #pragma unroll
                for (int nt = 0; nt < 8; nt++) {
                    int bn = (half*8 + nt)*8 + g4;
                    float2 tb = *(float2*)&Ks[bn*72 + ks*8 + l4*2];
                    float b[2] = {tb.x, tb.y};
                    mma8(sc[nt], qa[ks], b);
                }
            }

            // softmax: p = bit ? 2^s : 0   (log2e/32 pre-folded into Q)
            #pragma unroll
            for (int nt = 0; nt < 8; nt++) {
                int c = half*8 + nt;
                unsigned wd0 = (&w0.x)[c >> 2];
                unsigned wd1 = (&w1.x)[c >> 2];
                int bit = (c & 3)*8 + l4*2;
                sc[nt][0] = ((wd0 >> bit)     & 1) ? ex2f(sc[nt][0]) : 0.f;
                sc[nt][1] = ((wd0 >> (bit+1)) & 1) ? ex2f(sc[nt][1]) : 0.f;
                sc[nt][2] = ((wd1 >> bit)     & 1) ? ex2f(sc[nt][2]) : 0.f;
                sc[nt][3] = ((wd1 >> (bit+1)) & 1) ? ex2f(sc[nt][3]) : 0.f;
                rs0 += sc[nt][0] + sc[nt][1];
                rs1 += sc[nt][2] + sc[nt][3];
            }

            if (half == 0) {         // V(jt) needed from first PV onward
                CP_WAIT(1);
                __syncthreads();
            }

            // PV: A = D-fragment register rename (contraction permutation).
            #pragma unroll
            for (int j = 0; j < 8; j++) {
                float pa[4];
                pa[0] = to_tf32(sc[j][0]);
                pa[1] = to_tf32(sc[j][2]);
                pa[2] = to_tf32(sc[j][1]);
                pa[3] = to_tf32(sc[j][3]);
                int kb2 = (half*8 + j)*8 + 2*l4;
                #pragma unroll
                for (int nt8 = 0; nt8 < 8; nt8++) {
                    float2 tb = *(float2*)&Vt[(nt8*8 + g4)*136 + kb2];
                    float b[2] = {tb.x, tb.y};
                    mma8(oacc[nt8], pa, b);
                }
            }
        }
    }

    rs0 += __shfl_xor_sync(0xffffffffu, rs0, 1);
    rs0 += __shfl_xor_sync(0xffffffffu, rs0, 2);
    rs1 += __shfl_xor_sync(0xffffffffu, rs1, 1);
    rs1 += __shfl_xor_sync(0xffffffffu, rs1, 2);
    float inv0 = 1.f / rs0, inv1 = 1.f / rs1;

    float* ob0 = g_att + ((size_t)(n*SEQL + qb*128 + r0))*EMB + h*DH;
    float* ob1 = g_att + ((size_t)(n*SEQL + qb*128 + r1))*EMB + h*DH;
    int pc0 = 4*(l4 & 1) + (l4 >> 1);
    #pragma unroll
    for (int nt = 0; nt < 8; nt++) {
        int pc = nt*8 + pc0;
        ob0[pc]   = to_tf32(oacc[nt][0]*inv0);
        ob0[pc+2] = to_tf32(oacc[nt][1]*inv0);
        ob1[pc]   = to_tf32(oacc[nt][2]*inv1);
        ob1[pc+2] = to_tf32(oacc[nt][3]*inv1);
    }
}

// ---------------------------------------------------------------------------
// Output projection: pure-copy staging (operands pre-converted/permuted).
// ---------------------------------------------------------------------------
__global__ __launch_bounds__(256, 2)
void outproj_mma(const float* __restrict__ bo, float* __restrict__ out) {
    extern __shared__ float smo[];
    float* As = smo;             // [128][72]
    float* Bs = smo + 128*72;    // [128][72]
    int tid  = threadIdx.x;
    int lane = tid & 31, warp = tid >> 5;
    int g4 = lane >> 2, l4 = lane & 3;
    int wr = (warp >> 1) * 32, wc = (warp & 1) * 64;
    int rb = blockIdx.y, cb = blockIdx.x;

    const float* A = g_att + (size_t)rb*128*EMB;
    const float* B = g_wo  + (size_t)cb*128*EMB;

    float acc[2][8][4];
    #pragma unroll
    for (int m = 0; m < 2; m++)
        #pragma unroll
        for (int i = 0; i < 8; i++)
            #pragma unroll
            for (int j = 0; j < 4; j++) acc[m][i][j] = 0.f;

    for (int kt = 0; kt < 16; kt++) {
        __syncthreads();
        #pragma unroll
        for (int it = 0; it < 8; it++) {
            int g = tid + 256*it;
            int row = g >> 4, ds = (g & 15) * 4;
            *(float4*)&As[row*72 + ds] = *(const float4*)(A + (size_t)row*EMB + kt*64 + ds);
            *(float4*)&Bs[row*72 + ds] = *(const float4*)(B + (size_t)row*EMB + kt*64 + ds);
        }
        __syncthreads();

        #pragma unroll
        for (int ks = 0; ks < 8; ks++) {
            int ko = ks*8 + l4*2;
            float a0[4], a1[4];
            float2 t;
            t = *(float2*)&As[(wr + g4     )*72 + ko]; a0[0] = t.x; a0[2] = t.y;
            t = *(float2*)&As[(wr + g4 + 8 )*72 + ko]; a0[1] = t.x; a0[3] = t.y;
            t = *(float2*)&As[(wr + g4 + 16)*72 + ko]; a1[0] = t.x; a1[2] = t.y;
            t = *(float2*)&As[(wr + g4 + 24)*72 + ko]; a1[1] = t.x; a1[3] = t.y;
            #pragma unroll
            for (int nt = 0; nt < 8; nt++) {
                float2 tb = *(float2*)&Bs[(wc + nt*8 + g4)*72 + ko];
                float b[2] = {tb.x, tb.y};
                mma8(acc[0][nt], a0, b);
                mma8(acc[1][nt], a1, b);
            }
        }
    }

    #pragma unroll
    for (int mt = 0; mt < 2; mt++) {
        #pragma unroll
        for (int nt = 0; nt < 8; nt++) {
            int c = cb*128 + wc + nt*8 + l4*2;
            float b0 = bo[c], b1 = bo[c+1];
            int r = rb*128 + wr + mt*16 + g4;
            *(float2*)&out[(size_t)r*EMB + c] =
                make_float2(acc[mt][nt][0] + b0, acc[mt][nt][1] + b1);
            *(float2*)&out[(size_t)(r+8)*EMB + c] =
                make_float2(acc[mt][nt][2] + b0, acc[mt][nt][3] + b1);
        }
    }
}

// ---------------------------------------------------------------------------
extern "C" void kernel_launch(void* const* d_in, const int* in_sizes, int n_in,
                              void* d_out, int out_size) {
    const float* values = (const float*)d_in[0];
    const float* keys   = (const float*)d_in[1];
    const float* query  = (const float*)d_in[2];
    const int*   mask   = (const int*)  d_in[3];
    const float* Wv     = (const float*)d_in[4];
    const float* Wk     = (const float*)d_in[5];
    const float* Wq     = (const float*)d_in[6];
    const float* Wo     = (const float*)d_in[7];
    const float* bo     = (const float*)d_in[8];
    float* out = (float*)d_out;

    mask_pack<<<NB*SEQL*32/8, 256>>>(mask);
    wo_pack<<<EMB*EMB/1024, 256>>>(Wo);

    int smem_p = (128*72 + 2*64*72) * (int)sizeof(float);   // 73728 B
    cudaFuncSetAttribute(proj_mma, cudaFuncAttributeMaxDynamicSharedMemorySize, smem_p);
    proj_mma<<<dim3(64, NH, 3), 256, smem_p>>>(query, keys, values, Wq, Wk, Wv);

    int smem = (2*KSLOT + 64*136) * (int)sizeof(float);  // 108544 B
    cudaFuncSetAttribute(attn_mma_kernel, cudaFuncAttributeMaxDynamicSharedMemorySize, smem);
    attn_mma_kernel<<<dim3(SEQL/128, NB*NH), 256, smem>>>();

    int smem_o = 2 * 128*72 * (int)sizeof(float);       // 73728 B
    cudaFuncSetAttribute(outproj_mma, cudaFuncAttributeMaxDynamicSharedMemorySize, smem_o);
    outproj_mma<<<dim3(EMB/128, NB*SEQL/128), 256, smem_o>>>(bo, out);
}

// round 16
// speedup vs baseline: 1.1428x; 1.0114x over previous
#include <cuda_runtime.h>
#include <math.h>
#include <stdint.h>

#define NB    8
#define SEQL  1024
#define EMB   1024
#define NH    16
#define DH    64

// Quad-fragment layouts (16-col groups; thread l4's two-k-step fragment contiguous):
// g_q/g_k: [(bh), seq, 64]  cols quad-permuted: pos = (c&~15) + 4*(c&3) + ((c&15)>>2)
// g_v:     [(bh), 64, seq]  seq quad-permuted:  pos = (s&~15) + 4*((s&7)>>1) + (s&1) + 2*((s&15)>>3)
// g_att:   [n*seq, EMB] quad-permuted per 64-chunk; g_wo: [EMB, EMB] same
__device__ float g_q[NB*NH*SEQL*DH];
__device__ float g_k[NB*NH*SEQL*DH];
__device__ float g_v[NB*NH*SEQL*DH];
__device__ float g_att[NB*SEQL*EMB];
__device__ float g_wo[EMB*EMB];
__device__ unsigned g_mbits[NB*SEQL*32];

#define QSCALE 0.04508422f        // log2(e) / 32
#define QP16(c16) (4*((c16)&3) + ((c16)>>2))
#define VP16(s16) (4*(((s16)&7)>>1) + ((s16)&1) + 2*((s16)>>3))

// ---------------------------------------------------------------------------
__device__ __forceinline__ float to_tf32(float x) {
    uint32_t u;
    asm("cvt.rna.tf32.f32 %0, %1;" : "=r"(u) : "f"(x));
    return __uint_as_float(u);
}
__device__ __forceinline__ float ex2f(float x) {
    float r;
    asm("ex2.approx.f32 %0, %1;" : "=f"(r) : "f"(x));
    return r;
}
__device__ __forceinline__ uint32_t smem_u32(const void* p) {
    uint32_t a;
    asm("{ .reg .u64 t; cvta.to.shared.u64 t, %1; cvt.u32.u64 %0, t; }" : "=r"(a) : "l"(p));
    return a;
}
__device__ __forceinline__ void cpasync16(uint32_t saddr, const void* gptr) {
    asm volatile("cp.async.cg.shared.global [%0], [%1], 16;" :: "r"(saddr), "l"(gptr));
}
#define CP_COMMIT() asm volatile("cp.async.commit_group;" ::: "memory")
#define CP_WAIT(n)  asm volatile("cp.async.wait_group %0;" :: "n"(n) : "memory")

__device__ __forceinline__ void mma8(float* c, const float* a, const float* b) {
    asm volatile(
        "mma.sync.aligned.m16n8k8.row.col.f32.tf32.tf32.f32 "
        "{%0,%1,%2,%3}, {%4,%5,%6,%7}, {%8,%9}, {%0,%1,%2,%3};"
        : "+f"(c[0]), "+f"(c[1]), "+f"(c[2]), "+f"(c[3])
        : "f"(a[0]), "f"(a[1]), "f"(a[2]), "f"(a[3]), "f"(b[0]), "f"(b[1]));
}

// ---------------------------------------------------------------------------
__global__ __launch_bounds__(256)
void mask_pack(const int* __restrict__ mask) {
    int w    = blockIdx.x * 8 + (threadIdx.x >> 5);
    int lane = threadIdx.x & 31;
    unsigned bit = mask[(size_t)w*32 + lane] != 0;
    unsigned word = __ballot_sync(0xffffffffu, bit);
    if (lane == 0) g_mbits[w] = word;
}

__global__ __launch_bounds__(256)
void wo_pack(const float* __restrict__ Wo) {
    int idx = blockIdx.x * 256 + threadIdx.x;
    int row = idx >> 8, ds = (idx & 255) * 4;
    float4 w = *(const float4*)(Wo + (size_t)row*EMB + ds);
    int b16 = ds & ~15, c16 = ds & 15;
    float* p = g_wo + (size_t)row*EMB + b16;
    p[QP16(c16+0)] = to_tf32(w.x);
    p[QP16(c16+1)] = to_tf32(w.y);
    p[QP16(c16+2)] = to_tf32(w.z);
    p[QP16(c16+3)] = to_tf32(w.w);
}

// ---------------------------------------------------------------------------
// Fused Q/K/V projection via 3xTF32 compensated mma (fp32-accurate).
// Epilogues write quad-permuted layouts (Q scaled by log2e/32).
// ---------------------------------------------------------------------------
__global__ void __launch_bounds__(256, 2)
proj_mma(const float* __restrict__ xq, const float* __restrict__ xk,
         const float* __restrict__ xv,
         const float* __restrict__ Wq, const float* __restrict__ Wk,
         const float* __restrict__ Wv) {
    extern __shared__ float smp[];
    float* Xs  = smp;               // [128][72]
    float* Whi = smp + 128*72;      // [64][72]
    float* Wlo = Whi + 64*72;       // [64][72]

    int sel = blockIdx.z;
    const float* x = (sel == 0) ? xq : (sel == 1) ? xk : xv;
    const float* W = (sel == 0) ? Wq : (sel == 1) ? Wk : Wv;
    float*     out = (sel == 0) ? g_q : (sel == 1) ? g_k : g_v;

    int tid  = threadIdx.x;
    int lane = tid & 31, warp = tid >> 5;
    int g4 = lane >> 2, l4 = lane & 3;
    int wr = warp * 16;
    int rb = blockIdx.x, h = blockIdx.y;

    for (int g = tid; g < 1024; g += 256) {
        int e = g >> 4, ds = (g & 15) * 4;
        int pb = (ds & ~7) | ((ds >> 2) & 1);
        float4 w = *(const float4*)(W + e*64 + ds);
        float hx = to_tf32(w.x), hy = to_tf32(w.y), hz = to_tf32(w.z), hw = to_tf32(w.w);
        float* ph = &Whi[e*72 + pb];
        ph[0] = hx; ph[2] = hy; ph[4] = hz; ph[6] = hw;
        float* pl = &Wlo[e*72 + pb];
        pl[0] = to_tf32(w.x - hx); pl[2] = to_tf32(w.y - hy);
        pl[4] = to_tf32(w.z - hz); pl[6] = to_tf32(w.w - hw);
    }
    for (int g = tid; g < 2048; g += 256) {
        int row = g >> 4, ds = (g & 15) * 4;
        float4 v = *(const float4*)(x + (size_t)(rb*128 + row)*EMB + h*64 + ds);
        float* p = &Xs[row*72 + ((ds & ~7) | ((ds >> 2) & 1))];
        p[0] = v.x; p[2] = v.y; p[4] = v.z; p[6] = v.w;
    }
    __syncthreads();

    float ahi[8][4], alo[8][4];
    #pragma unroll
    for (int ks = 0; ks < 8; ks++) {
        float2 t0 = *(float2*)&Xs[(wr + g4    )*72 + ks*8 + l4*2];
        float2 t1 = *(float2*)&Xs[(wr + g4 + 8)*72 + ks*8 + l4*2];
        ahi[ks][0] = to_tf32(t0.x); alo[ks][0] = to_tf32(t0.x - ahi[ks][0]);
        ahi[ks][2] = to_tf32(t0.y); alo[ks][2] = to_tf32(t0.y - ahi[ks][2]);
        ahi[ks][1] = to_tf32(t1.x); alo[ks][1] = to_tf32(t1.x - ahi[ks][1]);
        ahi[ks][3] = to_tf32(t1.y); alo[ks][3] = to_tf32(t1.y - ahi[ks][3]);
    }

    float oacc[8][4];
    #pragma unroll
    for (int i = 0; i < 8; i++)
        #pragma unroll
        for (int j = 0; j < 4; j++) oacc[i][j] = 0.f;

    #pragma unroll
    for (int ks = 0; ks < 8; ks++) {
        #pragma unroll
        for (int nt = 0; nt < 8; nt++) {
            int bn = nt*8 + g4;
            float2 bh = *(float2*)&Whi[bn*72 + ks*8 + l4*2];
            float2 bl = *(float2*)&Wlo[bn*72 + ks*8 + l4*2];
            float vbh[2] = {bh.x, bh.y};
            float vbl[2] = {bl.x, bl.y};
            mma8(oacc[nt], ahi[ks], vbh);
            mma8(oacc[nt], alo[ks], vbh);
            mma8(oacc[nt], ahi[ks], vbl);
        }
    }

    int r0 = rb*128 + wr + g4;
    int r1 = r0 + 8;
    int n  = r0 >> 10;
    size_t base = ((size_t)(n*NH + h))*SEQL*DH;
    int l0 = r0 & 1023, l1 = r1 & 1023;

    if (sel < 2) {
        float scale = (sel == 0) ? QSCALE : 1.0f;
        float* o0 = out + base + (size_t)l0*DH;
        float* o1 = out + base + (size_t)l1*DH;
        #pragma unroll
        for (int nt = 0; nt < 8; nt++) {
            int b16 = (nt >> 1)*16;
            int c16 = (nt & 1)*8 + l4*2;
            int pA = b16 + QP16(c16), pB = b16 + QP16(c16+1);
            o0[pA] = to_tf32(oacc[nt][0] * scale);
            o0[pB] = to_tf32(oacc[nt][1] * scale);
            o1[pA] = to_tf32(oacc[nt][2] * scale);
            o1[pB] = to_tf32(oacc[nt][3] * scale);
        }
    } else {
        // V: [64][1024] seq quad-permuted
        int s0 = (l0 & ~15) + VP16(l0 & 15);
        int s1 = (l1 & ~15) + VP16(l1 & 15);
        #pragma unroll
        for (int nt = 0; nt < 8; nt++) {
            int e = nt*8 + l4*2;
            out[base + (size_t)(e  )*SEQL + s0] = to_tf32(oacc[nt][0]);
            out[base + (size_t)(e+1)*SEQL + s0] = to_tf32(oacc[nt][1]);
            out[base + (size_t)(e  )*SEQL + s1] = to_tf32(oacc[nt][2]);
            out[base + (size_t)(e+1)*SEQL + s1] = to_tf32(oacc[nt][3]);
        }
    }
}

// ---------------------------------------------------------------------------
// Flash attention: cp.async pipeline + quad fragments (LDS.128 feeds 2 mmas).
// SMEM: K [2 slots][kp 4][128][16] (32KB each), V [jp 8][64][16] (32KB).
// ---------------------------------------------------------------------------
#define KSLOT 8192
#define VOFF  16384

__global__ void __launch_bounds__(256, 2)
attn_mma_kernel() {
    extern __shared__ float sm[];

    int tid  = threadIdx.x;
    int lane = tid & 31, warp = tid >> 5;
    int g4 = lane >> 2, l4 = lane & 3;
    int wr = warp * 16;
    int bh = blockIdx.y, n = bh >> 4, h = bh & 15, qb = blockIdx.x;

    const float* Qg = g_q + (size_t)bh*SEQL*DH + (size_t)qb*128*DH;
    const float* Kg = g_k + (size_t)bh*SEQL*DH;
    const float* Vg = g_v + (size_t)bh*SEQL*DH;   // [64][1024]

    uint32_t sbase = smem_u32(sm);
    // staging decompositions (per-thread 8 chunks each for K and V)
    int krow[8], kkp[8], kq[8], vd[8], vjp[8], vq[8];
    #pragma unroll
    for (int it = 0; it < 8; it++) {
        int g = tid + 256*it;
        krow[it] = (g >> 2) & 127; kkp[it] = g >> 9;       kq[it] = g & 3;
        vd[it]   = (g >> 2) & 63;  vjp[it] = g >> 8;       vq[it] = g & 3;
    }

    // Prologue: K(0) -> slot 0
    #pragma unroll
    for (int it = 0; it < 8; it++)
        cpasync16(sbase + (uint32_t)(kkp[it]*2048 + krow[it]*16 + kq[it]*4)*4,
                  Kg + (size_t)krow[it]*DH + kkp[it]*16 + kq[it]*4);
    CP_COMMIT();

    // Q fragments: 8 LDG.128 (quad layout)
    float qa[8][4];
    #pragma unroll
    for (int kp = 0; kp < 4; kp++) {
        float4 t0 = *(const float4*)(Qg + (wr + g4    )*DH + kp*16 + l4*4);
        float4 t1 = *(const float4*)(Qg + (wr + g4 + 8)*DH + kp*16 + l4*4);
        qa[2*kp  ][0] = t0.x; qa[2*kp  ][2] = t0.y;
        qa[2*kp+1][0] = t0.z; qa[2*kp+1][2] = t0.w;
        qa[2*kp  ][1] = t1.x; qa[2*kp  ][3] = t1.y;
        qa[2*kp+1][1] = t1.z; qa[2*kp+1][3] = t1.w;
    }

    float oacc[8][4];
    #pragma unroll
    for (int i = 0; i < 8; i++)
        #pragma unroll
        for (int j = 0; j < 4; j++) oacc[i][j] = 0.f;
    float rs0 = 0.f, rs1 = 0.f;

    int r0 = wr + g4, r1 = r0 + 8;
    const unsigned* mb0 = g_mbits + ((size_t)n*SEQL + qb*128 + r0)*32;
    const unsigned* mb1 = g_mbits + ((size_t)n*SEQL + qb*128 + r1)*32;

    float* Vt = sm + VOFF;

    for (int jt = 0; jt < 8; jt++) {
        __syncthreads();

        // group A: V(jt)
        #pragma unroll
        for (int it = 0; it < 8; it++)
            cpasync16(sbase + (uint32_t)(VOFF + vjp[it]*1024 + vd[it]*16 + vq[it]*4)*4,
                      Vg + (size_t)vd[it]*SEQL + jt*128 + vjp[it]*16 + vq[it]*4);
        CP_COMMIT();
        // group B: K(jt+1)
        if (jt < 7) {
            uint32_t kb = (uint32_t)(((jt+1) & 1) * KSLOT);
            const float* Kn = Kg + (size_t)(jt+1)*128*DH;
            #pragma unroll
            for (int it = 0; it < 8; it++)
                cpasync16(sbase + (kb + (uint32_t)(kkp[it]*2048 + krow[it]*16 + kq[it]*4))*4,
                          Kn + (size_t)krow[it]*DH + kkp[it]*16 + kq[it]*4);
        }
        CP_COMMIT();

        uint4 w0 = *(const uint4*)(mb0 + jt*4);
        uint4 w1 = *(const uint4*)(mb1 + jt*4);

        CP_WAIT(2);          // K(jt) complete
        __syncthreads();
        float* Ks = sm + (jt & 1) * KSLOT;

        #pragma unroll
        for (int half = 0; half < 2; half++) {
            float sc[8][4];
            #pragma unroll
            for (int nt = 0; nt < 8; nt++)
                sc[nt][0] = sc[nt][1] = sc[nt][2] = sc[nt][3] = 0.f;
            #pragma unroll
            for (int kp = 0; kp < 4; kp++) {
                #pragma unroll
                for (int nt = 0; nt < 8; nt++) {
                    int bn = (half*8 + nt)*8 + g4;
                    float4 tb = *(float4*)&Ks[kp*2048 + bn*16 + l4*4];
                    float b0[2] = {tb.x, tb.y};
                    float b1[2] = {tb.z, tb.w};
                    mma8(sc[nt], qa[2*kp  ], b0);
                    mma8(sc[nt], qa[2*kp+1], b1);
                }
            }

            // softmax: p = bit ? 2^s : 0
            #pragma unroll
            for (int nt = 0; nt < 8; nt++) {
                int c = half*8 + nt;
                unsigned wd0 = (&w0.x)[c >> 2];
                unsigned wd1 = (&w1.x)[c >> 2];
                int bit = (c & 3)*8 + l4*2;
                sc[nt][0] = ((wd0 >> bit)     & 1) ? ex2f(sc[nt][0]) : 0.f;
                sc[nt][1] = ((wd0 >> (bit+1)) & 1) ? ex2f(sc[nt][1]) : 0.f;
                sc[nt][2] = ((wd1 >> bit)     & 1) ? ex2f(sc[nt][2]) : 0.f;
                sc[nt][3] = ((wd1 >> (bit+1)) & 1) ? ex2f(sc[nt][3]) : 0.f;
                rs0 += sc[nt][0] + sc[nt][1];
                rs1 += sc[nt][2] + sc[nt][3];
            }

            if (half == 0) {         // V(jt) needed from first PV onward
                CP_WAIT(1);
                __syncthreads();
            }

            // PV: A fragments from sc renames; quad V LDS.128 feeds 2 mmas.
            #pragma unroll
            for (int jp = 0; jp < 4; jp++) {
                float paA[4], paB[4];
                paA[0] = to_tf32(sc[2*jp][0]);   paA[1] = to_tf32(sc[2*jp][2]);
                paA[2] = to_tf32(sc[2*jp][1]);   paA[3] = to_tf32(sc[2*jp][3]);
                paB[0] = to_tf32(sc[2*jp+1][0]); paB[1] = to_tf32(sc[2*jp+1][2]);
                paB[2] = to_tf32(sc[2*jp+1][1]); paB[3] = to_tf32(sc[2*jp+1][3]);
                int off = (half*4 + jp)*1024 + g4*16 + l4*4;
                #pragma unroll
                for (int nt8 = 0; nt8 < 8; nt8++) {
                    float4 tb = *(float4*)&Vt[off + nt8*128];
                    float b0[2] = {tb.x, tb.y};
                    float b1[2] = {tb.z, tb.w};
                    mma8(oacc[nt8], paA, b0);
                    mma8(oacc[nt8], paB, b1);
                }
            }
        }
    }

    rs0 += __shfl_xor_sync(0xffffffffu, rs0, 1);
    rs0 += __shfl_xor_sync(0xffffffffu, rs0, 2);
    rs1 += __shfl_xor_sync(0xffffffffu, rs1, 1);
    rs1 += __shfl_xor_sync(0xffffffffu, rs1, 2);
    float inv0 = 1.f / rs0, inv1 = 1.f / rs1;

    // Epilogue: quad-permuted tf32 into g_att
    float* ob0 = g_att + ((size_t)(n*SEQL + qb*128 + r0))*EMB + h*DH;
    float* ob1 = g_att + ((size_t)(n*SEQL + qb*128 + r1))*EMB + h*DH;
    #pragma unroll
    for (int nt = 0; nt < 8; nt++) {
        int b16 = (nt >> 1)*16;
        int c16 = (nt & 1)*8 + l4*2;
        int pA = b16 + QP16(c16), pB = b16 + QP16(c16+1);
        ob0[pA] = to_tf32(oacc[nt][0]*inv0);
        ob0[pB] = to_tf32(oacc[nt][1]*inv0);
        ob1[pA] = to_tf32(oacc[nt][2]*inv1);
        ob1[pB] = to_tf32(oacc[nt][3]*inv1);
    }
}

// ---------------------------------------------------------------------------
// Output projection: quad-fragment tiles [kp][128][16], cp.async staging.
// ---------------------------------------------------------------------------
__global__ __launch_bounds__(256, 2)
void outproj_mma(const float* __restrict__ bo, float* __restrict__ out) {
    extern __shared__ float smo[];
    float* As = smo;             // [4][128][16]
    float* Bs = smo + 8192;      // [4][128][16]
    int tid  = threadIdx.x;
    int lane = tid & 31, warp = tid >> 5;
    int g4 = lane >> 2, l4 = lane & 3;
    int wr = (warp >> 1) * 32, wc = (warp & 1) * 64;
    int rb = blockIdx.y, cb = blockIdx.x;

    const float* A = g_att + (size_t)rb*128*EMB;
    const float* B = g_wo  + (size_t)cb*128*EMB;
    uint32_t sbase = smem_u32(smo);

    int srow[8], skp[8], sq[8];
    #pragma unroll
    for (int it = 0; it < 8; it++) {
        int g = tid + 256*it;
        srow[it] = (g >> 2) & 127; skp[it] = g >> 9; sq[it] = g & 3;
    }

    float acc[2][8][4];
    #pragma unroll
    for (int m = 0; m < 2; m++)
        #pragma unroll
        for (int i = 0; i < 8; i++)
            #pragma unroll
            for (int j = 0; j < 4; j++) acc[m][i][j] = 0.f;

    for (int kt = 0; kt < 16; kt++) {
        __syncthreads();
        #pragma unroll
        for (int it = 0; it < 8; it++) {
            uint32_t d = (uint32_t)(skp[it]*2048 + srow[it]*16 + sq[it]*4)*4;
            size_t s = (size_t)srow[it]*EMB + kt*64 + skp[it]*16 + sq[it]*4;
            cpasync16(sbase + d, A + s);
            cpasync16(sbase + 32768 + d, B + s);
        }
        CP_COMMIT();
        CP_WAIT(0);
        __syncthreads();

        #pragma unroll
        for (int kp = 0; kp < 4; kp++) {
            float4 tA0 = *(float4*)&As[kp*2048 + (wr + g4     )*16 + l4*4];
            float4 tA1 = *(float4*)&As[kp*2048 + (wr + g4 + 8 )*16 + l4*4];
            float4 tA2 = *(float4*)&As[kp*2048 + (wr + g4 + 16)*16 + l4*4];
            float4 tA3 = *(float4*)&As[kp*2048 + (wr + g4 + 24)*16 + l4*4];
            float ae0[4] = {tA0.x, tA1.x, tA0.y, tA1.y};
            float ao0[4] = {tA0.z, tA1.z, tA0.w, tA1.w};
            float ae1[4] = {tA2.x, tA3.x, tA2.y, tA3.y};
            float ao1[4] = {tA2.z, tA3.z, tA2.w, tA3.w};
            #pragma unroll
            for (int nt = 0; nt < 8; nt++) {
                float4 tb = *(float4*)&Bs[kp*2048 + (wc + nt*8 + g4)*16 + l4*4];
                float b0[2] = {tb.x, tb.y};
                float b1[2] = {tb.z, tb.w};
                mma8(acc[0][nt], ae0, b0);
                mma8(acc[0][nt], ao0, b1);
                mma8(acc[1][nt], ae1, b0);
                mma8(acc[1][nt], ao1, b1);
            }
        }
    }

    #pragma unroll
    for (int mt = 0; mt < 2; mt++) {
        #pragma unroll
        for (int nt = 0; nt < 8; nt++) {
            int c = cb*128 + wc + nt*8 + l4*2;
            float b0 = bo[c], b1 = bo[c+1];
            int r = rb*128 + wr + mt*16 + g4;
            *(float2*)&out[(size_t)r*EMB + c] =
                make_float2(acc[mt][nt][0] + b0, acc[mt][nt][1] + b1);
            *(float2*)&out[(size_t)(r+8)*EMB + c] =
                make_float2(acc[mt][nt][2] + b0, acc[mt][nt][3] + b1);
        }
    }
}

// ---------------------------------------------------------------------------
extern "C" void kernel_launch(void* const* d_in, const int* in_sizes, int n_in,
                              void* d_out, int out_size) {
    const float* values = (const float*)d_in[0];
    const float* keys   = (const float*)d_in[1];
    const float* query  = (const float*)d_in[2];
    const int*   mask   = (const int*)  d_in[3];
    const float* Wv     = (const float*)d_in[4];
    const float* Wk     = (const float*)d_in[5];
    const float* Wq     = (const float*)d_in[6];
    const float* Wo     = (const float*)d_in[7];
    const float* bo     = (const float*)d_in[8];
    float* out = (float*)d_out;

    mask_pack<<<NB*SEQL*32/8, 256>>>(mask);
    wo_pack<<<EMB*EMB/1024, 256>>>(Wo);

    int smem_p = (128*72 + 2*64*72) * (int)sizeof(float);   // 73728 B
    cudaFuncSetAttribute(proj_mma, cudaFuncAttributeMaxDynamicSharedMemorySize, smem_p);
    proj_mma<<<dim3(64, NH, 3), 256, smem_p>>>(query, keys, values, Wq, Wk, Wv);

    int smem = (2*KSLOT + 8192) * (int)sizeof(float);   // 98304 B
    cudaFuncSetAttribute(attn_mma_kernel, cudaFuncAttributeMaxDynamicSharedMemorySize, smem);
    attn_mma_kernel<<<dim3(SEQL/128, NB*NH), 256, smem>>>();

    int smem_o = 16384 * (int)sizeof(float);            // 65536 B
    cudaFuncSetAttribute(outproj_mma, cudaFuncAttributeMaxDynamicSharedMemorySize, smem_o);
    outproj_mma<<<dim3(EMB/128, NB*SEQL/128), 256, smem_o>>>(bo, out);
}